// round 11
// baseline (speedup 1.0000x reference)
#include <cuda_runtime.h>
#include <math.h>

#define Bv 65536
#define Tv 64
#define Uv 8
#define NB 8   // batches per warp (both kernels)

// Precomputed state.
__device__ float  g_wt[Tv][Uv];     // transposed flipped weights
__device__ float2 g_ab[Uv];         // (alpha*100, beta*10)
__device__ float  g_c[Bv * Uv];     // per-batch per-channel scale a/(1+b*z)

// ---------------------------------------------------------------------------
// Setup: per-channel constants once, then Kz, argmax -> t_idx, flipped weights.
// ---------------------------------------------------------------------------
__global__ void setup_kernel(const float* __restrict__ alpha,
                             const float* __restrict__ beta,
                             const float* __restrict__ gammap,
                             const float* __restrict__ tauZ,
                             const float* __restrict__ nZ,
                             const float* __restrict__ tauC,
                             const float* __restrict__ nC) {
    __shared__ float Kz[Tv][Uv];
    __shared__ int   tidx[Uv];
    __shared__ float s_tc[Uv], s_nc[Uv], s_normc[Uv];
    __shared__ float s_tz[Uv], s_nz[Uv], s_normz[Uv];
    __shared__ float s_g[Uv];

    int tid = threadIdx.x;  // 512 threads

    if (tid < Uv) {
        int u = tid;
        float tau_c = tauC[u] * 100.0f;
        float n_c   = nC[u]   * 10.0f;
        float tau_z = tauZ[u] * 100.0f;
        float n_z   = nZ[u]   * 10.0f;
        s_tc[u] = tau_c;  s_nc[u] = n_c;
        s_tz[u] = tau_z;  s_nz[u] = n_z;
        s_g[u]  = gammap[u] * 10.0f;
        s_normc[u] = __expf(-(n_c + 1.0f) * __logf(tau_c) - lgammaf(n_c + 1.0f));
        s_normz[u] = __expf(-(n_z + 1.0f) * __logf(tau_z) - lgammaf(n_z + 1.0f));
        g_ab[u] = make_float2(alpha[u] * 100.0f, beta[u] * 10.0f);
    }
    __syncthreads();

    if (tid < Tv * Uv) {
        int t = tid / Uv;
        int u = tid % Uv;
        float tf = (float)t;
        float kc = 0.0f, kz2 = 0.0f;
        if (t > 0) {
            float lt = __logf(tf);
            kc  = __expf(s_nc[u] * lt - tf / s_tc[u]) * s_normc[u];
            kz2 = __expf(s_nz[u] * lt - tf / s_tz[u]) * s_normz[u];
        }
        float g = s_g[u];
        Kz[t][u] = g * kc + (1.0f - g) * kz2;
    }
    __syncthreads();

    if (tid < Uv) {
        int u = tid;
        float best = Kz[0][u];
        int bi = 0;
        for (int t = 1; t < Tv; ++t) {
            if (Kz[t][u] > best) { best = Kz[t][u]; bi = t; }  // first max wins
        }
        int ti = Tv - bi;                 // T - z_shift
        if (ti > Tv - 1) ti = Tv - 1;
        if (ti < 0) ti = 0;
        tidx[u] = ti;
    }
    __syncthreads();

    if (tid < Tv * Uv) {
        int s = tid / Uv;
        int u = tid % Uv;
        int ti = tidx[u];
        g_wt[s][u] = (s <= ti) ? Kz[ti - s][u] : 0.0f;
    }
}

// ---------------------------------------------------------------------------
// Kernel A: per-batch scales.  z[u] = dot(x[b,:], w[:,u]);
// c[b][u] = a[u]/(1+b[u]*z[u]).  Packed butterfly (9 SHFL), lanes 0-7 store.
// ---------------------------------------------------------------------------
__global__ __launch_bounds__(256) void scale_kernel(const float* __restrict__ x) {
    int warp = blockIdx.x * (blockDim.x >> 5) + (threadIdx.x >> 5);
    int lane = threadIdx.x & 31;
    const unsigned FULL = 0xffffffffu;

    // Persistent weights: rows 2*lane, 2*lane+1, all 8 channels (16 regs)
    const float4* wp = (const float4*)g_wt;
    float4 w0a = wp[(2 * lane) * 2 + 0];
    float4 w0b = wp[(2 * lane) * 2 + 1];
    float4 w1a = wp[(2 * lane + 1) * 2 + 0];
    float4 w1b = wp[(2 * lane + 1) * 2 + 1];

    int b0 = lane & 1, b1 = (lane >> 1) & 1, b2 = (lane >> 2) & 1;
    int u = 4 * b0 + 2 * b1 + b2;       // this lane's channel after packed reduce
    float2 ab = g_ab[u];

    size_t base = (size_t)warp * NB;
    const float2* xb = (const float2*)(x + base * Tv);

    // Prefetch all NB x values
    float2 xv[NB];
#pragma unroll
    for (int n = 0; n < NB; ++n)
        xv[n] = xb[n * 32 + lane];

#pragma unroll
    for (int n = 0; n < NB; ++n) {
        float s[Uv];
        s[0] = fmaf(xv[n].x, w0a.x, xv[n].y * w1a.x);
        s[1] = fmaf(xv[n].x, w0a.y, xv[n].y * w1a.y);
        s[2] = fmaf(xv[n].x, w0a.z, xv[n].y * w1a.z);
        s[3] = fmaf(xv[n].x, w0a.w, xv[n].y * w1a.w);
        s[4] = fmaf(xv[n].x, w0b.x, xv[n].y * w1b.x);
        s[5] = fmaf(xv[n].x, w0b.y, xv[n].y * w1b.y);
        s[6] = fmaf(xv[n].x, w0b.z, xv[n].y * w1b.z);
        s[7] = fmaf(xv[n].x, w0b.w, xv[n].y * w1b.w);

        // Packed butterfly reduce: 9 SHFLs
#pragma unroll
        for (int j = 0; j < 4; ++j) {
            float send = b0 ? s[j] : s[j + 4];
            float recv = __shfl_xor_sync(FULL, send, 1);
            float keep = b0 ? s[j + 4] : s[j];
            s[j] = keep + recv;
        }
#pragma unroll
        for (int j = 0; j < 2; ++j) {
            float send = b1 ? s[j] : s[j + 2];
            float recv = __shfl_xor_sync(FULL, send, 2);
            float keep = b1 ? s[j + 2] : s[j];
            s[j] = keep + recv;
        }
        float z;
        {
            float send = b2 ? s[0] : s[1];
            float recv = __shfl_xor_sync(FULL, send, 4);
            float keep = b2 ? s[1] : s[0];
            z = keep + recv;
        }
        z += __shfl_xor_sync(FULL, z, 8);
        z += __shfl_xor_sync(FULL, z, 16);

        float myscale = __fdividef(ab.x, fmaf(ab.y, z, 1.0f));

        // Lanes 0-7 hold all 8 distinct channels; scatter-store 8 floats
        if (lane < 8)
            g_c[(base + n) * Uv + u] = myscale;
    }
}

// ---------------------------------------------------------------------------
// Kernel B (hot): pure streaming, zero shuffles.
//   out[b*512 + t*8 + u] = c[b][u] * x[b,t]
// Element e = i*128 + lane*4 + j  ->  u = 4*(lane&1)+j,  t = i*16 + (lane>>1).
// Each STG.128 across the warp writes one contiguous 512B block (full sectors).
// ---------------------------------------------------------------------------
__global__ __launch_bounds__(256) void out_kernel(const float* __restrict__ x,
                                                  float* __restrict__ out) {
    int warp = blockIdx.x * (blockDim.x >> 5) + (threadIdx.x >> 5);
    int lane = threadIdx.x & 31;

    size_t base = (size_t)warp * NB;
    const float*  xb = x + base * Tv;
    const float4* cb = (const float4*)g_c + base * 2 + (lane & 1);
    float* ob = out + base * (Tv * Uv);
    int th = lane >> 1;                 // x broadcast index term

#pragma unroll 2
    for (int n = 0; n < NB; ++n) {
        float4 cv = __ldg(cb + n * 2);  // c[b][4*(lane&1) .. +3]
        const float* xr = xb + n * Tv + th;

        // Prefetch the 4 x values (each a 16-lane broadcast load)
        float xt0 = __ldg(xr + 0);
        float xt1 = __ldg(xr + 16);
        float xt2 = __ldg(xr + 32);
        float xt3 = __ldg(xr + 48);

        float* on = ob + n * (Tv * Uv) + lane * 4;
        __stcs((float4*)(on + 0),   make_float4(xt0 * cv.x, xt0 * cv.y, xt0 * cv.z, xt0 * cv.w));
        __stcs((float4*)(on + 128), make_float4(xt1 * cv.x, xt1 * cv.y, xt1 * cv.z, xt1 * cv.w));
        __stcs((float4*)(on + 256), make_float4(xt2 * cv.x, xt2 * cv.y, xt2 * cv.z, xt2 * cv.w));
        __stcs((float4*)(on + 384), make_float4(xt3 * cv.x, xt3 * cv.y, xt3 * cv.z, xt3 * cv.w));
    }
}

extern "C" void kernel_launch(void* const* d_in, const int* in_sizes, int n_in,
                              void* d_out, int out_size) {
    // Input order: inputs, alpha, beta, gamma, zeta, tauY, nY, tauZ, nZ, tauC, nC
    const float* inputs = (const float*)d_in[0];
    const float* alpha  = (const float*)d_in[1];
    const float* beta   = (const float*)d_in[2];
    const float* gammap = (const float*)d_in[3];
    const float* tauZ   = (const float*)d_in[7];
    const float* nZ     = (const float*)d_in[8];
    const float* tauC   = (const float*)d_in[9];
    const float* nC     = (const float*)d_in[10];
    float* out = (float*)d_out;

    setup_kernel<<<1, 512>>>(alpha, beta, gammap, tauZ, nZ, tauC, nC);
    scale_kernel<<<Bv / (8 * NB), 256>>>(inputs);
    out_kernel<<<Bv / (8 * NB), 256>>>(inputs, out);
}

// round 14
// speedup vs baseline: 1.6764x; 1.6764x over previous
#include <cuda_runtime.h>
#include <math.h>

#define Bv 65536
#define Tv 64
#define Uv 8
#define NB 4   // batches per warp

// Precomputed state.
__device__ float  g_w[Uv][Tv];      // flipped weights, channel-major: w[u][s]
__device__ float2 g_ab[Uv];         // (alpha*100, beta*10)

// ---------------------------------------------------------------------------
// Setup: per-channel constants once, then Kz, argmax -> t_idx, flipped weights.
// ---------------------------------------------------------------------------
__global__ void setup_kernel(const float* __restrict__ alpha,
                             const float* __restrict__ beta,
                             const float* __restrict__ gammap,
                             const float* __restrict__ tauZ,
                             const float* __restrict__ nZ,
                             const float* __restrict__ tauC,
                             const float* __restrict__ nC) {
    __shared__ float Kz[Tv][Uv];
    __shared__ int   tidx[Uv];
    __shared__ float s_tc[Uv], s_nc[Uv], s_normc[Uv];
    __shared__ float s_tz[Uv], s_nz[Uv], s_normz[Uv];
    __shared__ float s_g[Uv];

    int tid = threadIdx.x;  // 512 threads

    if (tid < Uv) {
        int u = tid;
        float tau_c = tauC[u] * 100.0f;
        float n_c   = nC[u]   * 10.0f;
        float tau_z = tauZ[u] * 100.0f;
        float n_z   = nZ[u]   * 10.0f;
        s_tc[u] = tau_c;  s_nc[u] = n_c;
        s_tz[u] = tau_z;  s_nz[u] = n_z;
        s_g[u]  = gammap[u] * 10.0f;
        s_normc[u] = __expf(-(n_c + 1.0f) * __logf(tau_c) - lgammaf(n_c + 1.0f));
        s_normz[u] = __expf(-(n_z + 1.0f) * __logf(tau_z) - lgammaf(n_z + 1.0f));
        g_ab[u] = make_float2(alpha[u] * 100.0f, beta[u] * 10.0f);
    }
    __syncthreads();

    if (tid < Tv * Uv) {
        int t = tid / Uv;
        int u = tid % Uv;
        float tf = (float)t;
        float kc = 0.0f, kz2 = 0.0f;
        if (t > 0) {
            float lt = __logf(tf);
            kc  = __expf(s_nc[u] * lt - tf / s_tc[u]) * s_normc[u];
            kz2 = __expf(s_nz[u] * lt - tf / s_tz[u]) * s_normz[u];
        }
        float g = s_g[u];
        Kz[t][u] = g * kc + (1.0f - g) * kz2;
    }
    __syncthreads();

    if (tid < Uv) {
        int u = tid;
        float best = Kz[0][u];
        int bi = 0;
        for (int t = 1; t < Tv; ++t) {
            if (Kz[t][u] > best) { best = Kz[t][u]; bi = t; }  // first max wins
        }
        int ti = Tv - bi;                 // T - z_shift
        if (ti > Tv - 1) ti = Tv - 1;
        if (ti < 0) ti = 0;
        tidx[u] = ti;
    }
    __syncthreads();

    // Flipped weights, channel-major for contiguous per-lane LDG.128
    if (tid < Tv * Uv) {
        int s = tid / Uv;
        int u = tid % Uv;
        int ti = tidx[u];
        g_w[u][s] = (s <= ti) ? Kz[ti - s][u] : 0.0f;
    }
}

// ---------------------------------------------------------------------------
// Main: one warp per NB batches.
// Lane = q*8+u: channel u = lane&7, t-chunk q = lane>>3 (16 elems).
//   z[u] = dot(x[b,:], w[u,:])  -- partial per lane, 2-SHFL reduce over q
//   c[u] = a[u]/(1+b[u]*z[u])
//   out[b*512 + t*8 + u] = c[u] * x[b,t]
// ---------------------------------------------------------------------------
__global__ __launch_bounds__(256) void main_kernel(const float* __restrict__ x,
                                                   float* __restrict__ out) {
    int warp = blockIdx.x * (blockDim.x >> 5) + (threadIdx.x >> 5);
    int lane = threadIdx.x & 31;
    const unsigned FULL = 0xffffffffu;

    int u = lane & 7;
    int q = lane >> 3;

    // Persistent weights: w[u][16q .. 16q+15]  (4 float4 regs)
    const float4* wp = (const float4*)(&g_w[u][q * 16]);
    float4 wv0 = wp[0], wv1 = wp[1], wv2 = wp[2], wv3 = wp[3];

    float2 ab = g_ab[u];

    int hi  = lane & 1;          // store channel group
    int th  = lane >> 1;         // store t term

    size_t base = (size_t)warp * NB;
    const float* xb = x + base * Tv;
    float* ob = out + base * (Tv * Uv);

#pragma unroll
    for (int n = 0; n < NB; ++n) {
        const float* xr = xb + n * Tv;
        // Lane's 16 x values (octet-duplicated; 2 wf per LDG across warp)
        const float4* xq = (const float4*)(xr + q * 16);
        float4 x0 = xq[0], x1 = xq[1], x2 = xq[2], x3 = xq[3];

        // x[t] for stores: broadcast reloads (1 wf each, L1-hit).
        // Issued BEFORE the reduce chain so their latency overlaps it.
        float xt0 = __ldg(xr + th + 0);
        float xt1 = __ldg(xr + th + 16);
        float xt2 = __ldg(xr + th + 32);
        float xt3 = __ldg(xr + th + 48);

        // Partial dot over 16 elems, 4 accumulators for ILP
        float s0 = x0.x * wv0.x + x0.y * wv0.y;
        float s1 = x1.x * wv1.x + x1.y * wv1.y;
        float s2 = x2.x * wv2.x + x2.y * wv2.y;
        float s3 = x3.x * wv3.x + x3.y * wv3.y;
        s0 = fmaf(x0.z, wv0.z, fmaf(x0.w, wv0.w, s0));
        s1 = fmaf(x1.z, wv1.z, fmaf(x1.w, wv1.w, s1));
        s2 = fmaf(x2.z, wv2.z, fmaf(x2.w, wv2.w, s2));
        s3 = fmaf(x3.z, wv3.z, fmaf(x3.w, wv3.w, s3));
        float s = (s0 + s1) + (s2 + s3);

        // Reduce over the 4 octets: 2 SHFLs, chain depth 2
        s += __shfl_xor_sync(FULL, s, 8);
        s += __shfl_xor_sync(FULL, s, 16);

        // This lane's channel scale
        float c = __fdividef(ab.x, fmaf(ab.y, s, 1.0f));

        // Gather the 4 channels this lane stores: u_need = 4*hi + j (from lanes 0-7)
        float c0 = __shfl_sync(FULL, c, 4 * hi + 0);
        float c1 = __shfl_sync(FULL, c, 4 * hi + 1);
        float c2 = __shfl_sync(FULL, c, 4 * hi + 2);
        float c3 = __shfl_sync(FULL, c, 4 * hi + 3);

        // Element = i*128 + lane*4 + j -> t = i*16 + (lane>>1), u = 4*hi + j.
        // Each STG.128 across the warp writes one contiguous 512B block.
        float* on = ob + n * (Tv * Uv) + lane * 4;
        __stcs((float4*)(on + 0),   make_float4(xt0 * c0, xt0 * c1, xt0 * c2, xt0 * c3));
        __stcs((float4*)(on + 128), make_float4(xt1 * c0, xt1 * c1, xt1 * c2, xt1 * c3));
        __stcs((float4*)(on + 256), make_float4(xt2 * c0, xt2 * c1, xt2 * c2, xt2 * c3));
        __stcs((float4*)(on + 384), make_float4(xt3 * c0, xt3 * c1, xt3 * c2, xt3 * c3));
    }
}

extern "C" void kernel_launch(void* const* d_in, const int* in_sizes, int n_in,
                              void* d_out, int out_size) {
    // Input order: inputs, alpha, beta, gamma, zeta, tauY, nY, tauZ, nZ, tauC, nC
    const float* inputs = (const float*)d_in[0];
    const float* alpha  = (const float*)d_in[1];
    const float* beta   = (const float*)d_in[2];
    const float* gammap = (const float*)d_in[3];
    const float* tauZ   = (const float*)d_in[7];
    const float* nZ     = (const float*)d_in[8];
    const float* tauC   = (const float*)d_in[9];
    const float* nC     = (const float*)d_in[10];
    float* out = (float*)d_out;

    setup_kernel<<<1, 512>>>(alpha, beta, gammap, tauZ, nZ, tauC, nC);

    // 65536 batches / (8 warps * NB) = 2048 blocks
    main_kernel<<<Bv / (8 * NB), 256>>>(inputs, out);
}